// round 7
// baseline (speedup 1.0000x reference)
#include <cuda_runtime.h>

// Problem constants (fixed by setup_inputs)
#define NUM_CLASSES 19
#define BATCH 16
#define HH 1024
#define WW 2048
#define GSZ 8
#define HB (HH / GSZ)             // 128
#define WB (WW / GSZ)             // 256
#define NBLOCKS (BATCH * HB * WB) // 524288
#define TPB 256
#define NCTA (NBLOCKS / TPB)      // 2048
#define WARPS (TPB / 32)
#define FULL 0xffffffffu

// Allocation-free scratch; g_count reset by last block each launch.
__device__ float g_partials[NCTA];
__device__ unsigned g_count = 0;

__global__ void __launch_bounds__(TPB, 4)
fsenc_fused_kernel(const float* __restrict__ preds,
                   const int* __restrict__ targets,
                   float* __restrict__ out)
{
    __shared__ unsigned mask_sm[WARPS][32];
    __shared__ float warpsum[WARPS];
    __shared__ double dsm[TPB];
    __shared__ bool isLast;

    const int tid  = threadIdx.x;
    const int w    = tid >> 5;
    const int lane = tid & 31;

    // Warp handles 32 consecutive tiles [T0, T0+32), one (b, hb) row.
    const int T0 = blockIdx.x * TPB + (w << 5);
    const int wb0 = T0 & (WB - 1);
    const int t2  = T0 >> 8;          // / WB
    const int hb  = t2 & (HB - 1);
    const int b   = t2 >> 7;          // / HB

    const int* tb = targets + ((size_t)b * HH + (size_t)hb * GSZ) * WW
                            + (size_t)wb0 * GSZ;

    // ---- Batch ALL loads first: maximize memory-level parallelism ----
    // Targets: 16 lane-adjacent int4 (each instr = 512B contiguous, 4 lines).
    int4 ta[GSZ], tc[GSZ];
    #pragma unroll
    for (int r = 0; r < GSZ; r++) {
        const int4* p = reinterpret_cast<const int4*>(tb + (size_t)r * WW);
        ta[r] = __ldcs(p + lane);        // ints [4L,4L+4)   -> tile L/2
        tc[r] = __ldcs(p + 32 + lane);   // ints [128+4L,..) -> tile 16+L/2
    }
    // Preds: warp's 608 floats as 152 lane-adjacent float4 (T0%32==0 -> aligned).
    const float4* p4 =
        reinterpret_cast<const float4*>(preds + (size_t)T0 * NUM_CLASSES);
    float4 f[5];
    int   idxc[5];
    bool  valid[5];
    #pragma unroll
    for (int i = 0; i < 5; i++) {
        const int idx = lane + 32 * i;
        valid[i] = (idx < 152);
        idxc[i]  = valid[i] ? idx : 0;
        f[i] = __ldcs(p4 + idxc[i]);
    }

    // ---- Presence masks ----
    unsigned maskA = 0u, maskB = 0u;
    #pragma unroll
    for (int r = 0; r < GSZ; r++) {
        maskA |= (1u << ta[r].x) | (1u << ta[r].y) | (1u << ta[r].z) | (1u << ta[r].w);
        maskB |= (1u << tc[r].x) | (1u << tc[r].y) | (1u << tc[r].z) | (1u << tc[r].w);
    }
    // lanes 2t,2t+1 jointly cover tile t -> pair-OR, even lanes publish.
    const unsigned ma = maskA | __shfl_xor_sync(FULL, maskA, 1);
    const unsigned mb = maskB | __shfl_xor_sync(FULL, maskB, 1);
    if ((lane & 1) == 0) {
        mask_sm[w][lane >> 1]        = ma;   // tiles [0,16)
        mask_sm[w][16 + (lane >> 1)] = mb;   // tiles [16,32)
    }
    __syncwarp();

    // ---- loss = softplus(x) - present * x  (softplus is lane-agnostic) ----
    float s = 0.0f;
    #pragma unroll
    for (int i = 0; i < 5; i++) {
        const float v[4] = {f[i].x, f[i].y, f[i].z, f[i].w};
        float part = 0.0f;
        #pragma unroll
        for (int k = 0; k < 4; k++) {
            const int g   = 4 * idxc[i] + k;   // warp-local float idx [0,608)
            const int tl  = g / NUM_CLASSES;   // owning tile (const-div)
            const int cls = g - tl * NUM_CLASSES;
            const unsigned m = mask_sm[w][tl];
            const float x  = v[k];
            const float sp = fmaxf(x, 0.0f) + __logf(1.0f + __expf(-fabsf(x)));
            part += sp - (((m >> cls) & 1u) ? x : 0.0f);
        }
        s += valid[i] ? part : 0.0f;
    }

    // ---- Block reduce ----
    #pragma unroll
    for (int o = 16; o > 0; o >>= 1)
        s += __shfl_xor_sync(FULL, s, o);
    if (lane == 0) warpsum[w] = s;
    __syncthreads();

    if (tid == 0) {
        float vsum = 0.0f;
        #pragma unroll
        for (int i = 0; i < WARPS; i++) vsum += warpsum[i];
        g_partials[blockIdx.x] = vsum;
        __threadfence();
        unsigned n = atomicAdd(&g_count, 1u);
        isLast = (n == NCTA - 1);
    }
    __syncthreads();

    // ---- Last block: deterministic final reduce + mean ----
    if (isLast) {
        double d = 0.0;
        for (int i = tid; i < NCTA; i += TPB)
            d += (double)__ldcg(&g_partials[i]);
        dsm[tid] = d;
        __syncthreads();
        #pragma unroll
        for (int st = TPB / 2; st > 0; st >>= 1) {
            if (tid < st) dsm[tid] += dsm[tid + st];
            __syncthreads();
        }
        if (tid == 0) {
            out[0] = (float)(dsm[0] / ((double)NBLOCKS * (double)NUM_CLASSES));
            g_count = 0;   // reset for next graph replay
        }
    }
}

extern "C" void kernel_launch(void* const* d_in, const int* in_sizes, int n_in,
                              void* d_out, int out_size)
{
    const float* preds   = (const float*)d_in[0];
    const int*   targets = (const int*)d_in[1];
    // d_in[2] = grid_size (known constant 8)

    fsenc_fused_kernel<<<NCTA, TPB>>>(preds, targets, (float*)d_out);
}

// round 8
// speedup vs baseline: 1.0189x; 1.0189x over previous
#include <cuda_runtime.h>

// Problem constants (fixed by setup_inputs)
#define NUM_CLASSES 19
#define BATCH 16
#define HH 1024
#define WW 2048
#define GSZ 8
#define HB (HH / GSZ)             // 128
#define WB (WW / GSZ)             // 256
#define NBLOCKS (BATCH * HB * WB) // 524288
#define TPB 256
#define TILES_PER_THREAD 2
#define NCTA (NBLOCKS / (TPB * TILES_PER_THREAD))  // 1024 -> single wave
#define WARPS (TPB / 32)
#define FULL 0xffffffffu

// Allocation-free scratch; g_count reset by last block each launch.
__device__ float g_partials[NCTA];
__device__ unsigned g_count = 0;

// 7 CTAs/SM (regs <= 36): 1024 CTAs fit in ONE wave on 148 SMs.
__global__ void __launch_bounds__(TPB, 7)
fsenc_fused_kernel(const float* __restrict__ preds,
                   const int* __restrict__ targets,
                   float* __restrict__ out)
{
    __shared__ float warpsum[WARPS];
    __shared__ double dsm[TPB];
    __shared__ bool isLast;

    const int tid  = threadIdx.x;
    const int w    = tid >> 5;
    const int lane = tid & 31;

    float s = 0.0f;

    #pragma unroll
    for (int j = 0; j < TILES_PER_THREAD; j++) {
        const int tile = blockIdx.x * (TPB * TILES_PER_THREAD) + j * TPB + tid;

        // tile -> (b, hb, wb): row-major over (BATCH, HB, WB)
        const int wb = tile & (WB - 1);
        const int t2 = tile >> 8;           // / WB (WB=256)
        const int hb = t2 & (HB - 1);
        const int b  = t2 >> 7;             // / HB (HB=128)

        const int* tbase = targets + ((size_t)b * HH + (size_t)hb * GSZ) * WW
                                   + (size_t)wb * GSZ;

        // ---- 19-bit presence mask over the 8x8 target tile ----
        unsigned mask = 0u;
        #pragma unroll
        for (int r = 0; r < GSZ; r++) {
            const int4* p = reinterpret_cast<const int4*>(tbase + (size_t)r * WW);
            int4 a = __ldcs(p);
            int4 c = __ldcs(p + 1);
            mask |= (1u << a.x) | (1u << a.y) | (1u << a.z) | (1u << a.w);
            mask |= (1u << c.x) | (1u << c.y) | (1u << c.z) | (1u << c.w);
        }

        // ---- loss_c = softplus(x_c) - present_c * x_c ----
        const float* prow = preds + (size_t)tile * NUM_CLASSES;
        #pragma unroll
        for (int c = 0; c < NUM_CLASSES; c++) {
            float x  = __ldcs(prow + c);
            float sv = fmaxf(x, 0.0f) + __logf(1.0f + __expf(-fabsf(x)));
            s += sv - (((mask >> c) & 1u) ? x : 0.0f);
        }
    }

    // ---- Block reduce ----
    #pragma unroll
    for (int o = 16; o > 0; o >>= 1)
        s += __shfl_xor_sync(FULL, s, o);
    if (lane == 0) warpsum[w] = s;
    __syncthreads();

    if (tid == 0) {
        float vsum = 0.0f;
        #pragma unroll
        for (int i = 0; i < WARPS; i++) vsum += warpsum[i];
        g_partials[blockIdx.x] = vsum;
        __threadfence();
        unsigned n = atomicAdd(&g_count, 1u);
        isLast = (n == NCTA - 1);
    }
    __syncthreads();

    // ---- Last block: deterministic final reduce + mean ----
    if (isLast) {
        double d = 0.0;
        for (int i = tid; i < NCTA; i += TPB)
            d += (double)__ldcg(&g_partials[i]);
        dsm[tid] = d;
        __syncthreads();
        #pragma unroll
        for (int st = TPB / 2; st > 0; st >>= 1) {
            if (tid < st) dsm[tid] += dsm[tid + st];
            __syncthreads();
        }
        if (tid == 0) {
            out[0] = (float)(dsm[0] / ((double)NBLOCKS * (double)NUM_CLASSES));
            g_count = 0;   // reset for next graph replay
        }
    }
}

extern "C" void kernel_launch(void* const* d_in, const int* in_sizes, int n_in,
                              void* d_out, int out_size)
{
    const float* preds   = (const float*)d_in[0];
    const int*   targets = (const int*)d_in[1];
    // d_in[2] = grid_size (known constant 8)

    fsenc_fused_kernel<<<NCTA, TPB>>>(preds, targets, (float*)d_out);
}